// round 1
// baseline (speedup 1.0000x reference)
#include <cuda_runtime.h>
#include <math.h>

// Problem constants
// B=2, S=2048, D=1024, H=16, HD=64

// Scratch (device globals — no allocation allowed)
__device__ float g_qkv[(size_t)2 * 2048 * 3072];      // [B*S, 3D]
__device__ float g_q[(size_t)2 * 16 * 2048 * 64];     // q heads, rotated
__device__ float g_y[(size_t)2 * 2048 * 1024];        // attention output [B*S, D]

// ---------------------------------------------------------------------------
// Tiled SGEMM: C[M,N] = A[M,K] * B[K,N] + bias[N]
// BM=BN=64, BK=16, 256 threads, 4x4 register tile per thread.
// ---------------------------------------------------------------------------
__global__ __launch_bounds__(256) void sgemm_bias(
    const float* __restrict__ A, const float* __restrict__ B,
    const float* __restrict__ bias, float* __restrict__ C,
    int M, int N, int K)
{
    __shared__ float As[16][68];   // transposed A tile, padded
    __shared__ float Bs[16][64];

    const int tid = threadIdx.x;
    const int tx = tid & 15, ty = tid >> 4;
    const int bm = blockIdx.y << 6, bn = blockIdx.x << 6;

    const int arow = tid >> 2;            // 0..63
    const int acol = (tid & 3) << 2;      // 0,4,8,12
    const int brow = tid >> 4;            // 0..15
    const int bcol = (tid & 15) << 2;     // 0..60

    const float* Ag = A + (size_t)(bm + arow) * K + acol;
    const float* Bg = B + (size_t)brow * N + bn + bcol;

    float acc[4][4] = {};

    for (int k0 = 0; k0 < K; k0 += 16) {
        float4 av = *(const float4*)(Ag + k0);
        float4 bv = *(const float4*)(Bg + (size_t)k0 * N);
        As[acol + 0][arow] = av.x;
        As[acol + 1][arow] = av.y;
        As[acol + 2][arow] = av.z;
        As[acol + 3][arow] = av.w;
        *(float4*)&Bs[brow][bcol] = bv;
        __syncthreads();

        #pragma unroll
        for (int kk = 0; kk < 16; kk++) {
            float4 a = *(const float4*)&As[kk][ty << 2];
            float4 b = *(const float4*)&Bs[kk][tx << 2];
            float ar[4] = {a.x, a.y, a.z, a.w};
            float br[4] = {b.x, b.y, b.z, b.w};
            #pragma unroll
            for (int i = 0; i < 4; i++)
                #pragma unroll
                for (int j = 0; j < 4; j++)
                    acc[i][j] += ar[i] * br[j];
        }
        __syncthreads();
    }

    #pragma unroll
    for (int i = 0; i < 4; i++) {
        int row = bm + (ty << 2) + i;
        int col = bn + (tx << 2);
        float4 out;
        out.x = acc[i][0] + bias[col + 0];
        out.y = acc[i][1] + bias[col + 1];
        out.z = acc[i][2] + bias[col + 2];
        out.w = acc[i][3] + bias[col + 3];
        *(float4*)&C[(size_t)row * N + col] = out;
    }
}

// ---------------------------------------------------------------------------
// RoPE + head-layout scatter.
// One thread per (b,s,h,pair): rotates q,k; copies v. Writes q to scratch,
// k/v directly to the output buffer in (B,H,S,HD) layout.
// ---------------------------------------------------------------------------
__global__ __launch_bounds__(256) void rope_scatter(
    const float* __restrict__ qkv,
    const float* __restrict__ cs, const float* __restrict__ sn,
    float* __restrict__ qh, float* __restrict__ kout, float* __restrict__ vout)
{
    int idx = blockIdx.x * blockDim.x + threadIdx.x;  // B*S*H*32 = 2^21
    int p = idx & 31;
    int h = (idx >> 5) & 15;
    int s = (idx >> 9) & 2047;
    int b = idx >> 20;

    const float* base = qkv + ((size_t)(b * 2048 + s)) * 3072 + h * 64 + 2 * p;
    float c0 = cs[s * 64 + 2 * p], c1 = cs[s * 64 + 2 * p + 1];
    float s0 = sn[s * 64 + 2 * p], s1 = sn[s * 64 + 2 * p + 1];

    float q0 = base[0],    q1 = base[1];
    float k0 = base[1024], k1 = base[1025];
    float v0 = base[2048], v1 = base[2049];

    size_t o = (((size_t)(b * 16 + h)) * 2048 + s) * 64 + 2 * p;
    qh[o]     = q0 * c0 - q1 * s0;
    qh[o + 1] = q1 * c1 + q0 * s1;
    kout[o]     = k0 * c0 - k1 * s0;
    kout[o + 1] = k1 * c1 + k0 * s1;
    vout[o]     = v0;
    vout[o + 1] = v1;
}

// ---------------------------------------------------------------------------
// Flash-attention style: one CTA = 64 query rows of one (b,h).
// Online softmax over 32 KV tiles of 64. 256 threads, 4x4 micro-tiles.
// ---------------------------------------------------------------------------
__global__ __launch_bounds__(256) void attn_kernel(
    const float* __restrict__ qh, const float* __restrict__ kh,
    const float* __restrict__ vh, float* __restrict__ y)
{
    extern __shared__ float sm[];
    float* Qt  = sm;                 // [64][68]  Q transposed (hd-major)
    float* Kst = sm + 64 * 68;       // [64][68]  K transposed (hd-major)
    float* Pt  = sm + 2 * 64 * 68;   // [64][68]  P transposed (kvcol-major)
    float* Vs  = sm + 3 * 64 * 68;   // [64][64]  V row-major

    const int tid = threadIdx.x;
    const int tx = tid & 15, ty = tid >> 4;
    const int bh = blockIdx.y;       // b*16 + h
    const int s0 = blockIdx.x << 6;

    const float* qb = qh + ((size_t)bh * 2048 + s0) * 64;
    const float* kb = kh + (size_t)bh * 2048 * 64;
    const float* vb = vh + (size_t)bh * 2048 * 64;

    const int lr = tid >> 4;             // 0..15
    const int lc = (tid & 15) << 2;      // 0..60

    #pragma unroll
    for (int it = 0; it < 4; it++) {
        int r = (it << 4) + lr;
        float4 v = *(const float4*)(qb + r * 64 + lc);
        Qt[(lc + 0) * 68 + r] = v.x;
        Qt[(lc + 1) * 68 + r] = v.y;
        Qt[(lc + 2) * 68 + r] = v.z;
        Qt[(lc + 3) * 68 + r] = v.w;
    }

    float m[4], l[4], o[4][4];
    #pragma unroll
    for (int i = 0; i < 4; i++) {
        m[i] = -1e30f; l[i] = 0.f;
        #pragma unroll
        for (int j = 0; j < 4; j++) o[i][j] = 0.f;
    }

    for (int t = 0; t < 32; t++) {
        __syncthreads();  // previous PV done before overwriting tiles
        const float* kt = kb + (size_t)t * 64 * 64;
        const float* vt = vb + (size_t)t * 64 * 64;
        #pragma unroll
        for (int it = 0; it < 4; it++) {
            int r = (it << 4) + lr;
            float4 kv = *(const float4*)(kt + r * 64 + lc);
            Kst[(lc + 0) * 68 + r] = kv.x;
            Kst[(lc + 1) * 68 + r] = kv.y;
            Kst[(lc + 2) * 68 + r] = kv.z;
            Kst[(lc + 3) * 68 + r] = kv.w;
            *(float4*)&Vs[r * 64 + lc] = *(const float4*)(vt + r * 64 + lc);
        }
        __syncthreads();

        // S = Q K^T (scaled)
        float s[4][4] = {};
        #pragma unroll 8
        for (int kk = 0; kk < 64; kk++) {
            float4 a = *(const float4*)&Qt[kk * 68 + (ty << 2)];
            float4 b = *(const float4*)&Kst[kk * 68 + (tx << 2)];
            float ar[4] = {a.x, a.y, a.z, a.w};
            float br[4] = {b.x, b.y, b.z, b.w};
            #pragma unroll
            for (int i = 0; i < 4; i++)
                #pragma unroll
                for (int j = 0; j < 4; j++)
                    s[i][j] += ar[i] * br[j];
        }

        // online softmax (row reduce across 16 tx lanes — same half-warp)
        #pragma unroll
        for (int i = 0; i < 4; i++) {
            #pragma unroll
            for (int j = 0; j < 4; j++) s[i][j] *= 0.125f;
            float mx = fmaxf(fmaxf(s[i][0], s[i][1]), fmaxf(s[i][2], s[i][3]));
            #pragma unroll
            for (int off = 1; off < 16; off <<= 1)
                mx = fmaxf(mx, __shfl_xor_sync(0xffffffffu, mx, off));
            float nm = fmaxf(m[i], mx);
            float alpha = __expf(m[i] - nm);
            float rs = 0.f;
            #pragma unroll
            for (int j = 0; j < 4; j++) {
                s[i][j] = __expf(s[i][j] - nm);
                rs += s[i][j];
            }
            #pragma unroll
            for (int off = 1; off < 16; off <<= 1)
                rs += __shfl_xor_sync(0xffffffffu, rs, off);
            l[i] = l[i] * alpha + rs;
            m[i] = nm;
            #pragma unroll
            for (int j = 0; j < 4; j++) {
                o[i][j] *= alpha;
                Pt[((tx << 2) + j) * 68 + (ty << 2) + i] = s[i][j];
            }
        }
        __syncthreads();

        // O += P V
        #pragma unroll 8
        for (int c = 0; c < 64; c++) {
            float4 a = *(const float4*)&Pt[c * 68 + (ty << 2)];
            float4 b = *(const float4*)&Vs[c * 64 + (tx << 2)];
            float ar[4] = {a.x, a.y, a.z, a.w};
            float br[4] = {b.x, b.y, b.z, b.w};
            #pragma unroll
            for (int i = 0; i < 4; i++)
                #pragma unroll
                for (int j = 0; j < 4; j++)
                    o[i][j] += ar[i] * br[j];
        }
    }

    // epilogue: write back into [B,S,D] layout for the proj GEMM
    const int b = bh >> 4, h = bh & 15;
    #pragma unroll
    for (int i = 0; i < 4; i++) {
        float inv = 1.f / l[i];
        size_t row = (size_t)(b * 2048 + s0 + (ty << 2) + i);
        float4 out;
        out.x = o[i][0] * inv;
        out.y = o[i][1] * inv;
        out.z = o[i][2] * inv;
        out.w = o[i][3] * inv;
        *(float4*)&y[row * 1024 + h * 64 + (tx << 2)] = out;
    }
}

// ---------------------------------------------------------------------------
extern "C" void kernel_launch(void* const* d_in, const int* in_sizes, int n_in,
                              void* d_out, int out_size)
{
    const float* x     = (const float*)d_in[0];
    const float* cs    = (const float*)d_in[1];
    const float* sn    = (const float*)d_in[2];
    const float* Wqkv  = (const float*)d_in[3];
    const float* bqkv  = (const float*)d_in[4];
    const float* Wproj = (const float*)d_in[5];
    const float* bproj = (const float*)d_in[6];

    float* out   = (float*)d_out;
    float* out_y = out;                                   // [B,S,D]
    float* out_k = out + (size_t)2 * 2048 * 1024;         // [B,H,S,HD]
    float* out_v = out_k + (size_t)2 * 16 * 2048 * 64;    // [B,H,S,HD]

    float *qkv, *qheads, *ybuf;
    cudaGetSymbolAddress((void**)&qkv, g_qkv);
    cudaGetSymbolAddress((void**)&qheads, g_q);
    cudaGetSymbolAddress((void**)&ybuf, g_y);

    // 1) QKV GEMM: [4096,1024] x [1024,3072] + bias
    sgemm_bias<<<dim3(3072 / 64, 4096 / 64), 256>>>(
        x, Wqkv, bqkv, qkv, 4096, 3072, 1024);

    // 2) RoPE + scatter into head layouts (k,v straight to output)
    rope_scatter<<<8192, 256>>>(qkv, cs, sn, qheads, out_k, out_v);

    // 3) Attention
    const int attn_smem = (3 * 64 * 68 + 64 * 64) * 4;  // 68608 B
    cudaFuncSetAttribute(attn_kernel,
                         cudaFuncAttributeMaxDynamicSharedMemorySize, attn_smem);
    attn_kernel<<<dim3(2048 / 64, 2 * 16), 256, attn_smem>>>(
        qheads, out_k, out_v, ybuf);

    // 4) Output projection: [4096,1024] x [1024,1024] + bias
    sgemm_bias<<<dim3(1024 / 64, 4096 / 64), 256>>>(
        ybuf, Wproj, bproj, out_y, 4096, 1024, 1024);
}

// round 3
// speedup vs baseline: 1.1511x; 1.1511x over previous
#include <cuda_runtime.h>
#include <math.h>

// B=2, S=2048, D=1024, H=16, HD=64

__device__ float g_qkv[(size_t)2 * 2048 * 3072];      // [B*S, 3D]
__device__ float g_q[(size_t)2 * 16 * 2048 * 64];     // q heads, rotated+scaled
__device__ float g_y[(size_t)2 * 2048 * 1024];        // attention out [B*S, D]

// ---------------------------------------------------------------------------
// SGEMM: C[M,N] = A[M,K]*B[K,N] + bias. BM=BN=128, BK=16, 256 thr, 8x8.
// ---------------------------------------------------------------------------
__global__ __launch_bounds__(256) void sgemm_bias(
    const float* __restrict__ A, const float* __restrict__ B,
    const float* __restrict__ bias, float* __restrict__ C,
    int M, int N, int K)
{
    __shared__ float As[16][132];   // [k][m], transposed, padded (132*4B % 16 == 0)
    __shared__ float Bs[16][128];   // [k][n]

    const int tid = threadIdx.x;
    const int tx = tid & 15, ty = tid >> 4;
    const int bm = blockIdx.y << 7, bn = blockIdx.x << 7;

    float acc[8][8] = {};

    for (int k0 = 0; k0 < K; k0 += 16) {
        #pragma unroll
        for (int i = 0; i < 2; i++) {
            int idx = tid * 2 + i;                 // 0..511
            int ar = idx >> 2, ac = (idx & 3) << 2;
            float4 av = *(const float4*)(A + (size_t)(bm + ar) * K + k0 + ac);
            As[ac + 0][ar] = av.x;
            As[ac + 1][ar] = av.y;
            As[ac + 2][ar] = av.z;
            As[ac + 3][ar] = av.w;
            int br = idx >> 5, bc = (idx & 31) << 2;
            float4 bv = *(const float4*)(B + (size_t)(k0 + br) * N + bn + bc);
            *(float4*)&Bs[br][bc] = bv;
        }
        __syncthreads();

        #pragma unroll
        for (int kk = 0; kk < 16; kk++) {
            float4 a0 = *(const float4*)&As[kk][ty << 3];
            float4 a1 = *(const float4*)&As[kk][(ty << 3) + 4];
            float4 b0 = *(const float4*)&Bs[kk][tx << 2];
            float4 b1 = *(const float4*)&Bs[kk][64 + (tx << 2)];
            float ar[8] = {a0.x, a0.y, a0.z, a0.w, a1.x, a1.y, a1.z, a1.w};
            float br[8] = {b0.x, b0.y, b0.z, b0.w, b1.x, b1.y, b1.z, b1.w};
            #pragma unroll
            for (int i = 0; i < 8; i++)
                #pragma unroll
                for (int j = 0; j < 8; j++)
                    acc[i][j] += ar[i] * br[j];
        }
        __syncthreads();
    }

    const int c0 = bn + (tx << 2);
    float4 bs0 = *(const float4*)&bias[c0];
    float4 bs1 = *(const float4*)&bias[c0 + 64];
    #pragma unroll
    for (int i = 0; i < 8; i++) {
        size_t row = (size_t)(bm + (ty << 3) + i);
        float4 o0, o1;
        o0.x = acc[i][0] + bs0.x; o0.y = acc[i][1] + bs0.y;
        o0.z = acc[i][2] + bs0.z; o0.w = acc[i][3] + bs0.w;
        o1.x = acc[i][4] + bs1.x; o1.y = acc[i][5] + bs1.y;
        o1.z = acc[i][6] + bs1.z; o1.w = acc[i][7] + bs1.w;
        *(float4*)&C[row * N + c0] = o0;
        *(float4*)&C[row * N + c0 + 64] = o1;
    }
}

// ---------------------------------------------------------------------------
// RoPE + head scatter. q scaled by 1/sqrt(HD).
// ---------------------------------------------------------------------------
__global__ __launch_bounds__(256) void rope_scatter(
    const float* __restrict__ qkv,
    const float* __restrict__ cs, const float* __restrict__ sn,
    float* __restrict__ qh, float* __restrict__ kout, float* __restrict__ vout)
{
    int idx = blockIdx.x * blockDim.x + threadIdx.x;  // 2^21
    int p = idx & 31;
    int h = (idx >> 5) & 15;
    int s = (idx >> 9) & 2047;
    int b = idx >> 20;

    const float* base = qkv + ((size_t)(b * 2048 + s)) * 3072 + h * 64 + 2 * p;
    float c0 = cs[s * 64 + 2 * p], c1 = cs[s * 64 + 2 * p + 1];
    float s0 = sn[s * 64 + 2 * p], s1 = sn[s * 64 + 2 * p + 1];

    float q0 = base[0],    q1 = base[1];
    float k0 = base[1024], k1 = base[1025];
    float v0 = base[2048], v1 = base[2049];

    size_t o = (((size_t)(b * 16 + h)) * 2048 + s) * 64 + 2 * p;
    qh[o]     = (q0 * c0 - q1 * s0) * 0.125f;
    qh[o + 1] = (q1 * c1 + q0 * s1) * 0.125f;
    kout[o]     = k0 * c0 - k1 * s0;
    kout[o + 1] = k1 * c1 + k0 * s1;
    vout[o]     = v0;
    vout[o + 1] = v1;
}

// ---------------------------------------------------------------------------
// Flash attention: CTA = 128 q-rows of one (b,h). kv tiles of 64.
// 256 threads, 8x4 micro-tiles. Online softmax.
// All smem row strides are multiples of 4 floats (16B) for LDS.128.
// ---------------------------------------------------------------------------
__global__ __launch_bounds__(256) void attn_kernel(
    const float* __restrict__ qh, const float* __restrict__ kh,
    const float* __restrict__ vh, float* __restrict__ y)
{
    extern __shared__ float sm[];
    float* Qt  = sm;                       // [64][132]  hd-major, q transposed
    float* Kst = Qt + 64 * 132;            // [64][68]   hd-major, k transposed
    float* Vs  = Kst + 64 * 68;            // [64][68]   row-major
    float* Ps  = Vs + 64 * 68;             // [128][68]  row-major P

    const int tid = threadIdx.x;
    const int tx = tid & 15, ty = tid >> 4;
    const int bh = blockIdx.y;
    const int s0 = blockIdx.x << 7;

    const float* qb = qh + ((size_t)bh * 2048 + s0) * 64;
    const float* kb = kh + (size_t)bh * 2048 * 64;
    const float* vb = vh + (size_t)bh * 2048 * 64;

    const int lr = tid >> 4;               // 0..15
    const int lc = (tid & 15) << 2;        // 0..60

    #pragma unroll
    for (int it = 0; it < 8; it++) {
        int r = (it << 4) + lr;
        float4 v = *(const float4*)(qb + r * 64 + lc);
        Qt[(lc + 0) * 132 + r] = v.x;
        Qt[(lc + 1) * 132 + r] = v.y;
        Qt[(lc + 2) * 132 + r] = v.z;
        Qt[(lc + 3) * 132 + r] = v.w;
    }

    float m[8], l[8], o[8][4];
    #pragma unroll
    for (int i = 0; i < 8; i++) {
        m[i] = -1e30f; l[i] = 0.f;
        o[i][0] = o[i][1] = o[i][2] = o[i][3] = 0.f;
    }

    for (int t = 0; t < 32; t++) {
        __syncthreads();
        const float* kt = kb + (size_t)t * 4096;
        const float* vt = vb + (size_t)t * 4096;
        #pragma unroll
        for (int it = 0; it < 4; it++) {
            int r = (it << 4) + lr;
            float4 kv = *(const float4*)(kt + r * 64 + lc);
            Kst[(lc + 0) * 68 + r] = kv.x;
            Kst[(lc + 1) * 68 + r] = kv.y;
            Kst[(lc + 2) * 68 + r] = kv.z;
            Kst[(lc + 3) * 68 + r] = kv.w;
            *(float4*)&Vs[r * 68 + lc] = *(const float4*)(vt + r * 64 + lc);
        }
        __syncthreads();

        // S = Q K^T  (q pre-scaled)
        float s[8][4] = {};
        #pragma unroll 8
        for (int kk = 0; kk < 64; kk++) {
            float4 a0 = *(const float4*)&Qt[kk * 132 + (ty << 3)];
            float4 a1 = *(const float4*)&Qt[kk * 132 + (ty << 3) + 4];
            float4 b  = *(const float4*)&Kst[kk * 68 + (tx << 2)];
            float ar[8] = {a0.x, a0.y, a0.z, a0.w, a1.x, a1.y, a1.z, a1.w};
            float br[4] = {b.x, b.y, b.z, b.w};
            #pragma unroll
            for (int i = 0; i < 8; i++)
                #pragma unroll
                for (int j = 0; j < 4; j++)
                    s[i][j] += ar[i] * br[j];
        }

        // online softmax (reduce across 16 tx lanes)
        #pragma unroll
        for (int i = 0; i < 8; i++) {
            float mx = fmaxf(fmaxf(s[i][0], s[i][1]), fmaxf(s[i][2], s[i][3]));
            #pragma unroll
            for (int off = 1; off < 16; off <<= 1)
                mx = fmaxf(mx, __shfl_xor_sync(0xffffffffu, mx, off));
            float nm = fmaxf(m[i], mx);
            float alpha = __expf(m[i] - nm);
            float rs = 0.f;
            #pragma unroll
            for (int j = 0; j < 4; j++) {
                s[i][j] = __expf(s[i][j] - nm);
                rs += s[i][j];
            }
            #pragma unroll
            for (int off = 1; off < 16; off <<= 1)
                rs += __shfl_xor_sync(0xffffffffu, rs, off);
            l[i] = l[i] * alpha + rs;
            m[i] = nm;
            #pragma unroll
            for (int j = 0; j < 4; j++) o[i][j] *= alpha;
            *(float4*)&Ps[((ty << 3) + i) * 68 + (tx << 2)] =
                make_float4(s[i][0], s[i][1], s[i][2], s[i][3]);
        }
        __syncthreads();

        // O += P V
        for (int c0 = 0; c0 < 64; c0 += 4) {
            float4 pa[8];
            #pragma unroll
            for (int i = 0; i < 8; i++)
                pa[i] = *(const float4*)&Ps[((ty << 3) + i) * 68 + c0];
            #pragma unroll
            for (int cc = 0; cc < 4; cc++) {
                float4 bv = *(const float4*)&Vs[(c0 + cc) * 68 + (tx << 2)];
                #pragma unroll
                for (int i = 0; i < 8; i++) {
                    float p = (cc == 0) ? pa[i].x : (cc == 1) ? pa[i].y
                            : (cc == 2) ? pa[i].z : pa[i].w;
                    o[i][0] += p * bv.x;
                    o[i][1] += p * bv.y;
                    o[i][2] += p * bv.z;
                    o[i][3] += p * bv.w;
                }
            }
        }
    }

    const int b = bh >> 4, h = bh & 15;
    #pragma unroll
    for (int i = 0; i < 8; i++) {
        float inv = 1.f / l[i];
        size_t row = (size_t)(b * 2048 + s0 + (ty << 3) + i);
        float4 out;
        out.x = o[i][0] * inv;
        out.y = o[i][1] * inv;
        out.z = o[i][2] * inv;
        out.w = o[i][3] * inv;
        *(float4*)&y[row * 1024 + h * 64 + (tx << 2)] = out;
    }
}

// ---------------------------------------------------------------------------
extern "C" void kernel_launch(void* const* d_in, const int* in_sizes, int n_in,
                              void* d_out, int out_size)
{
    const float* x     = (const float*)d_in[0];
    const float* cs    = (const float*)d_in[1];
    const float* sn    = (const float*)d_in[2];
    const float* Wqkv  = (const float*)d_in[3];
    const float* bqkv  = (const float*)d_in[4];
    const float* Wproj = (const float*)d_in[5];
    const float* bproj = (const float*)d_in[6];

    float* out   = (float*)d_out;
    float* out_y = out;
    float* out_k = out + (size_t)2 * 2048 * 1024;
    float* out_v = out_k + (size_t)2 * 16 * 2048 * 64;

    float *qkv, *qheads, *ybuf;
    cudaGetSymbolAddress((void**)&qkv, g_qkv);
    cudaGetSymbolAddress((void**)&qheads, g_q);
    cudaGetSymbolAddress((void**)&ybuf, g_y);

    // 1) QKV GEMM [4096,1024]x[1024,3072]
    sgemm_bias<<<dim3(3072 / 128, 4096 / 128), 256>>>(
        x, Wqkv, bqkv, qkv, 4096, 3072, 1024);

    // 2) RoPE + scatter
    rope_scatter<<<8192, 256>>>(qkv, cs, sn, qheads, out_k, out_v);

    // 3) Attention
    const int attn_smem = (64 * 132 + 64 * 68 + 64 * 68 + 128 * 68) * 4;
    cudaFuncSetAttribute(attn_kernel,
                         cudaFuncAttributeMaxDynamicSharedMemorySize, attn_smem);
    attn_kernel<<<dim3(2048 / 128, 2 * 16), 256, attn_smem>>>(
        qheads, out_k, out_v, ybuf);

    // 4) Projection [4096,1024]x[1024,1024]
    sgemm_bias<<<dim3(1024 / 128, 4096 / 128), 256>>>(
        ybuf, Wproj, bproj, out_y, 4096, 1024, 1024);
}

// round 5
// speedup vs baseline: 1.5721x; 1.3658x over previous
#include <cuda_runtime.h>
#include <cuda_bf16.h>
#include <math.h>
#include <stdint.h>

// B=2, S=2048, D=1024, H=16, HD=64

// ---------------- scratch (device globals) ----------------
__device__ float g_qkv[(size_t)2 * 2048 * 3072];      // [B*S, 3D]
__device__ float g_q[(size_t)2 * 16 * 2048 * 64];     // q heads (rot+scaled)
__device__ float g_y[(size_t)2 * 2048 * 1024];        // attn out [B*S, D]

__device__ __nv_bfloat16 g_xhi[4194304], g_xlo[4194304];       // x split
__device__ __nv_bfloat16 g_wqt_hi[3145728], g_wqt_lo[3145728]; // Wqkv^T split
__device__ __nv_bfloat16 g_wpt_hi[1048576], g_wpt_lo[1048576]; // Wproj^T split
__device__ __nv_bfloat16 g_yhi[4194304], g_ylo[4194304];       // y split

// ---------------- base-ISA tensor-core helpers ----------------
__device__ __forceinline__ uint32_t smem_u32(const void* p) {
    uint32_t a;
    asm("{ .reg .u64 t; cvta.to.shared.u64 t, %1; cvt.u32.u64 %0, t; }"
        : "=r"(a) : "l"(p));
    return a;
}

#define CP_ASYNC16(dst, src) \
    asm volatile("cp.async.cg.shared.global [%0], [%1], 16;" \
                 :: "r"(dst), "l"(src))
#define CP_COMMIT() asm volatile("cp.async.commit_group;" ::: "memory")
#define CP_WAIT(n)  asm volatile("cp.async.wait_group %0;" :: "n"(n) : "memory")

__device__ __forceinline__ void ldmx4(uint32_t* r, uint32_t addr) {
    asm volatile("ldmatrix.sync.aligned.m8n8.x4.shared.b16 {%0,%1,%2,%3}, [%4];"
                 : "=r"(r[0]), "=r"(r[1]), "=r"(r[2]), "=r"(r[3]) : "r"(addr));
}

__device__ __forceinline__ void mma16816(float* d, const uint32_t* a,
                                         const uint32_t* b) {
    asm volatile(
        "mma.sync.aligned.m16n8k16.row.col.f32.bf16.bf16.f32 "
        "{%0,%1,%2,%3}, {%4,%5,%6,%7}, {%8,%9}, {%0,%1,%2,%3};"
        : "+f"(d[0]), "+f"(d[1]), "+f"(d[2]), "+f"(d[3])
        : "r"(a[0]), "r"(a[1]), "r"(a[2]), "r"(a[3]), "r"(b[0]), "r"(b[1]));
}

// ---------------------------------------------------------------------------
// Split-precision conversion kernels
// ---------------------------------------------------------------------------
__global__ __launch_bounds__(256) void convert_split(
    const float* __restrict__ in, __nv_bfloat16* __restrict__ hi,
    __nv_bfloat16* __restrict__ lo)
{
    int i = (blockIdx.x * blockDim.x + threadIdx.x) << 2;
    float4 v = *(const float4*)(in + i);
    __nv_bfloat16 h0 = __float2bfloat16(v.x);
    __nv_bfloat16 h1 = __float2bfloat16(v.y);
    __nv_bfloat16 h2 = __float2bfloat16(v.z);
    __nv_bfloat16 h3 = __float2bfloat16(v.w);
    __nv_bfloat16 l0 = __float2bfloat16(v.x - __bfloat162float(h0));
    __nv_bfloat16 l1 = __float2bfloat16(v.y - __bfloat162float(h1));
    __nv_bfloat16 l2 = __float2bfloat16(v.z - __bfloat162float(h2));
    __nv_bfloat16 l3 = __float2bfloat16(v.w - __bfloat162float(h3));
    __nv_bfloat162* H = (__nv_bfloat162*)(hi + i);
    __nv_bfloat162* L = (__nv_bfloat162*)(lo + i);
    __nv_bfloat162 a; a.x = h0; a.y = h1;
    __nv_bfloat162 b; b.x = h2; b.y = h3;
    __nv_bfloat162 c; c.x = l0; c.y = l1;
    __nv_bfloat162 d; d.x = l2; d.y = l3;
    H[0] = a; H[1] = b; L[0] = c; L[1] = d;
}

// W[K][N] f32 -> Wt_hi/lo[N][K] bf16 (transpose + split)
__global__ __launch_bounds__(256) void transpose_split(
    const float* __restrict__ W, __nv_bfloat16* __restrict__ Thi,
    __nv_bfloat16* __restrict__ Tlo, int K, int N)
{
    __shared__ float t[32][33];
    int n0 = blockIdx.x << 5, k0 = blockIdx.y << 5;
    int tx = threadIdx.x, ty = threadIdx.y;   // 32 x 8
    #pragma unroll
    for (int i = 0; i < 4; i++)
        t[ty + 8 * i][tx] = W[(size_t)(k0 + ty + 8 * i) * N + n0 + tx];
    __syncthreads();
    #pragma unroll
    for (int i = 0; i < 4; i++) {
        float v = t[tx][ty + 8 * i];
        __nv_bfloat16 h = __float2bfloat16(v);
        __nv_bfloat16 l = __float2bfloat16(v - __bfloat162float(h));
        size_t o = (size_t)(n0 + ty + 8 * i) * K + k0 + tx;
        Thi[o] = h;
        Tlo[o] = l;
    }
}

// ---------------------------------------------------------------------------
// Split-bf16 GEMM via mma.sync: C[M,N] = A[M,K]*B^T[N,K] + bias
// 128x128 CTA tile, BK=32, 8 warps (2x4), 64x32 warp tile, double-buffered.
// smem tiles: 128 rows x 80B stride (64B data) -> ldmatrix conflict-free.
// ---------------------------------------------------------------------------
#define TILE_B 10240          // 128 * 80
#define STAGE_B 40960         // 4 tiles

__device__ __forceinline__ void gemm_load_chunk(
    uint32_t sst,
    const __nv_bfloat16* __restrict__ Ahi, const __nv_bfloat16* __restrict__ Alo,
    const __nv_bfloat16* __restrict__ Bhi, const __nv_bfloat16* __restrict__ Blo,
    int bm, int bn, int K, int k0, int tid)
{
    #pragma unroll
    for (int j = 0; j < 2; j++) {
        int u = tid + (j << 8);              // 0..511
        int r = u >> 2;                      // 0..127
        int c16 = (u & 3) << 4;              // 0,16,32,48
        uint32_t d = sst + (uint32_t)r * 80 + c16;
        size_t ga = ((size_t)(bm + r) * K + k0) * 2 + c16;
        size_t gb = ((size_t)(bn + r) * K + k0) * 2 + c16;
        CP_ASYNC16(d,               (const char*)Ahi + ga);
        CP_ASYNC16(d + TILE_B,      (const char*)Alo + ga);
        CP_ASYNC16(d + 2 * TILE_B,  (const char*)Bhi + gb);
        CP_ASYNC16(d + 3 * TILE_B,  (const char*)Blo + gb);
    }
}

__global__ __launch_bounds__(256) void gemm_mma(
    const __nv_bfloat16* __restrict__ Ahi, const __nv_bfloat16* __restrict__ Alo,
    const __nv_bfloat16* __restrict__ Bhi, const __nv_bfloat16* __restrict__ Blo,
    const float* __restrict__ bias, float* __restrict__ C,
    int M, int N, int K)
{
    extern __shared__ char smem[];
    const uint32_t sb = smem_u32(smem);

    const int tid = threadIdx.x;
    const int wid = tid >> 5;
    const int lane = tid & 31;
    const int bm = blockIdx.y << 7, bn = blockIdx.x << 7;
    const int wm = (wid >> 2) << 6;          // 0 or 64
    const int wn = (wid & 3) << 5;           // 0,32,64,96

    float acc[4][4][4] = {};                 // [mtile][ntile][frag]

    // prefetch chunk 0
    gemm_load_chunk(sb, Ahi, Alo, Bhi, Blo, bm, bn, K, 0, tid);
    CP_COMMIT();

    const int nchunk = K >> 5;
    for (int c = 0; c < nchunk; c++) {
        const uint32_t st = sb + (uint32_t)(c & 1) * STAGE_B;
        if (c + 1 < nchunk) {
            gemm_load_chunk(sb + (uint32_t)((c + 1) & 1) * STAGE_B,
                            Ahi, Alo, Bhi, Blo, bm, bn, K, (c + 1) << 5, tid);
            CP_COMMIT();
            CP_WAIT(1);
        } else {
            CP_WAIT(0);
        }
        __syncthreads();

        #pragma unroll
        for (int ks = 0; ks < 2; ks++) {
            const int kb = ks << 5;          // byte offset of k16 slice
            // A fragments (hi, lo)
            uint32_t af[2][4][4];
            #pragma unroll
            for (int s = 0; s < 2; s++) {
                uint32_t abase = st + (uint32_t)s * TILE_B;
                #pragma unroll
                for (int mt = 0; mt < 4; mt++) {
                    uint32_t addr = abase
                        + (uint32_t)(wm + (mt << 4) + (lane & 15)) * 80
                        + kb + ((lane >> 4) << 4);
                    ldmx4(af[s][mt], addr);
                }
            }
            // B fragments (hi, lo): two x4 loads cover n 0..15 / 16..31
            uint32_t bf[2][8];
            #pragma unroll
            for (int s = 0; s < 2; s++) {
                uint32_t bbase = st + (uint32_t)(2 + s) * TILE_B;
                #pragma unroll
                for (int g = 0; g < 2; g++) {
                    uint32_t nrow = wn + (g << 4) + (((lane >> 4) & 1) << 3)
                                  + (lane & 7);
                    uint32_t addr = bbase + nrow * 80 + kb
                                  + (((lane >> 3) & 1) << 4);
                    ldmx4(&bf[s][g << 2], addr);
                }
            }
            // 3-pass split MMA
            #pragma unroll
            for (int mt = 0; mt < 4; mt++)
                #pragma unroll
                for (int nt = 0; nt < 4; nt++) {
                    mma16816(acc[mt][nt], af[0][mt], &bf[0][nt << 1]);
                    mma16816(acc[mt][nt], af[0][mt], &bf[1][nt << 1]);
                    mma16816(acc[mt][nt], af[1][mt], &bf[0][nt << 1]);
                }
        }
        __syncthreads();
    }

    // epilogue: frag (row = l/4 (+8), col = 2*(l%4)) + bias
    const int r0 = bm + wm + (lane >> 2);
    const int cc0 = bn + wn + ((lane & 3) << 1);
    #pragma unroll
    for (int mt = 0; mt < 4; mt++) {
        #pragma unroll
        for (int nt = 0; nt < 4; nt++) {
            int col = cc0 + (nt << 3);
            float b0 = bias[col], b1 = bias[col + 1];
            int ra = r0 + (mt << 4);
            float2 v0 = make_float2(acc[mt][nt][0] + b0, acc[mt][nt][1] + b1);
            float2 v1 = make_float2(acc[mt][nt][2] + b0, acc[mt][nt][3] + b1);
            *(float2*)&C[(size_t)ra * N + col] = v0;
            *(float2*)&C[(size_t)(ra + 8) * N + col] = v1;
        }
    }
}

// ---------------------------------------------------------------------------
// RoPE + head scatter. q scaled by 1/sqrt(HD).
// ---------------------------------------------------------------------------
__global__ __launch_bounds__(256) void rope_scatter(
    const float* __restrict__ qkv,
    const float* __restrict__ cs, const float* __restrict__ sn,
    float* __restrict__ qh, float* __restrict__ kout, float* __restrict__ vout)
{
    int idx = blockIdx.x * blockDim.x + threadIdx.x;
    int p = idx & 31;
    int h = (idx >> 5) & 15;
    int s = (idx >> 9) & 2047;
    int b = idx >> 20;

    const float* base = qkv + ((size_t)(b * 2048 + s)) * 3072 + h * 64 + 2 * p;
    float c0 = cs[s * 64 + 2 * p], c1 = cs[s * 64 + 2 * p + 1];
    float s0 = sn[s * 64 + 2 * p], s1 = sn[s * 64 + 2 * p + 1];

    float q0 = base[0],    q1 = base[1];
    float k0 = base[1024], k1 = base[1025];
    float v0 = base[2048], v1 = base[2049];

    size_t o = (((size_t)(b * 16 + h)) * 2048 + s) * 64 + 2 * p;
    qh[o]     = (q0 * c0 - q1 * s0) * 0.125f;
    qh[o + 1] = (q1 * c1 + q0 * s1) * 0.125f;
    kout[o]     = k0 * c0 - k1 * s0;
    kout[o + 1] = k1 * c1 + k0 * s1;
    vout[o]     = v0;
    vout[o + 1] = v1;
}

// ---------------------------------------------------------------------------
// Flash attention (fp32): CTA = 128 q-rows of one (b,h). kv tiles of 64.
// ---------------------------------------------------------------------------
__global__ __launch_bounds__(256) void attn_kernel(
    const float* __restrict__ qh, const float* __restrict__ kh,
    const float* __restrict__ vh, float* __restrict__ y)
{
    extern __shared__ float sm[];
    float* Qt  = sm;                       // [64][132]
    float* Kst = Qt + 64 * 132;            // [64][68]
    float* Vs  = Kst + 64 * 68;            // [64][68]
    float* Ps  = Vs + 64 * 68;             // [128][68]

    const int tid = threadIdx.x;
    const int tx = tid & 15, ty = tid >> 4;
    const int bh = blockIdx.y;
    const int s0 = blockIdx.x << 7;

    const float* qb = qh + ((size_t)bh * 2048 + s0) * 64;
    const float* kb = kh + (size_t)bh * 2048 * 64;
    const float* vb = vh + (size_t)bh * 2048 * 64;

    const int lr = tid >> 4;
    const int lc = (tid & 15) << 2;

    #pragma unroll
    for (int it = 0; it < 8; it++) {
        int r = (it << 4) + lr;
        float4 v = *(const float4*)(qb + r * 64 + lc);
        Qt[(lc + 0) * 132 + r] = v.x;
        Qt[(lc + 1) * 132 + r] = v.y;
        Qt[(lc + 2) * 132 + r] = v.z;
        Qt[(lc + 3) * 132 + r] = v.w;
    }

    float m[8], l[8], o[8][4];
    #pragma unroll
    for (int i = 0; i < 8; i++) {
        m[i] = -1e30f; l[i] = 0.f;
        o[i][0] = o[i][1] = o[i][2] = o[i][3] = 0.f;
    }

    for (int t = 0; t < 32; t++) {
        __syncthreads();
        const float* kt = kb + (size_t)t * 4096;
        const float* vt = vb + (size_t)t * 4096;
        #pragma unroll
        for (int it = 0; it < 4; it++) {
            int r = (it << 4) + lr;
            float4 kv = *(const float4*)(kt + r * 64 + lc);
            Kst[(lc + 0) * 68 + r] = kv.x;
            Kst[(lc + 1) * 68 + r] = kv.y;
            Kst[(lc + 2) * 68 + r] = kv.z;
            Kst[(lc + 3) * 68 + r] = kv.w;
            *(float4*)&Vs[r * 68 + lc] = *(const float4*)(vt + r * 64 + lc);
        }
        __syncthreads();

        float s[8][4] = {};
        #pragma unroll 8
        for (int kk = 0; kk < 64; kk++) {
            float4 a0 = *(const float4*)&Qt[kk * 132 + (ty << 3)];
            float4 a1 = *(const float4*)&Qt[kk * 132 + (ty << 3) + 4];
            float4 b  = *(const float4*)&Kst[kk * 68 + (tx << 2)];
            float ar[8] = {a0.x, a0.y, a0.z, a0.w, a1.x, a1.y, a1.z, a1.w};
            float br[4] = {b.x, b.y, b.z, b.w};
            #pragma unroll
            for (int i = 0; i < 8; i++)
                #pragma unroll
                for (int j = 0; j < 4; j++)
                    s[i][j] += ar[i] * br[j];
        }

        #pragma unroll
        for (int i = 0; i < 8; i++) {
            float mx = fmaxf(fmaxf(s[i][0], s[i][1]), fmaxf(s[i][2], s[i][3]));
            #pragma unroll
            for (int off = 1; off < 16; off <<= 1)
                mx = fmaxf(mx, __shfl_xor_sync(0xffffffffu, mx, off));
            float nm = fmaxf(m[i], mx);
            float alpha = __expf(m[i] - nm);
            float rs = 0.f;
            #pragma unroll
            for (int j = 0; j < 4; j++) {
                s[i][j] = __expf(s[i][j] - nm);
                rs += s[i][j];
            }
            #pragma unroll
            for (int off = 1; off < 16; off <<= 1)
                rs += __shfl_xor_sync(0xffffffffu, rs, off);
            l[i] = l[i] * alpha + rs;
            m[i] = nm;
            #pragma unroll
            for (int j = 0; j < 4; j++) o[i][j] *= alpha;
            *(float4*)&Ps[((ty << 3) + i) * 68 + (tx << 2)] =
                make_float4(s[i][0], s[i][1], s[i][2], s[i][3]);
        }
        __syncthreads();

        for (int c0 = 0; c0 < 64; c0 += 4) {
            float4 pa[8];
            #pragma unroll
            for (int i = 0; i < 8; i++)
                pa[i] = *(const float4*)&Ps[((ty << 3) + i) * 68 + c0];
            #pragma unroll
            for (int cc = 0; cc < 4; cc++) {
                float4 bv = *(const float4*)&Vs[(c0 + cc) * 68 + (tx << 2)];
                #pragma unroll
                for (int i = 0; i < 8; i++) {
                    float p = (cc == 0) ? pa[i].x : (cc == 1) ? pa[i].y
                            : (cc == 2) ? pa[i].z : pa[i].w;
                    o[i][0] += p * bv.x;
                    o[i][1] += p * bv.y;
                    o[i][2] += p * bv.z;
                    o[i][3] += p * bv.w;
                }
            }
        }
    }

    const int b = bh >> 4, h = bh & 15;
    #pragma unroll
    for (int i = 0; i < 8; i++) {
        float inv = 1.f / l[i];
        size_t row = (size_t)(b * 2048 + s0 + (ty << 3) + i);
        float4 out;
        out.x = o[i][0] * inv;
        out.y = o[i][1] * inv;
        out.z = o[i][2] * inv;
        out.w = o[i][3] * inv;
        *(float4*)&y[row * 1024 + h * 64 + (tx << 2)] = out;
    }
}

// ---------------------------------------------------------------------------
extern "C" void kernel_launch(void* const* d_in, const int* in_sizes, int n_in,
                              void* d_out, int out_size)
{
    const float* x     = (const float*)d_in[0];
    const float* cs    = (const float*)d_in[1];
    const float* sn    = (const float*)d_in[2];
    const float* Wqkv  = (const float*)d_in[3];
    const float* bqkv  = (const float*)d_in[4];
    const float* Wproj = (const float*)d_in[5];
    const float* bproj = (const float*)d_in[6];

    float* out   = (float*)d_out;
    float* out_y = out;
    float* out_k = out + (size_t)2 * 2048 * 1024;
    float* out_v = out_k + (size_t)2 * 16 * 2048 * 64;

    float *qkv, *qheads, *ybuf;
    cudaGetSymbolAddress((void**)&qkv, g_qkv);
    cudaGetSymbolAddress((void**)&qheads, g_q);
    cudaGetSymbolAddress((void**)&ybuf, g_y);
    __nv_bfloat16 *xhi, *xlo, *wqh, *wql, *wph, *wpl, *yhi, *ylo;
    cudaGetSymbolAddress((void**)&xhi, g_xhi);
    cudaGetSymbolAddress((void**)&xlo, g_xlo);
    cudaGetSymbolAddress((void**)&wqh, g_wqt_hi);
    cudaGetSymbolAddress((void**)&wql, g_wqt_lo);
    cudaGetSymbolAddress((void**)&wph, g_wpt_hi);
    cudaGetSymbolAddress((void**)&wpl, g_wpt_lo);
    cudaGetSymbolAddress((void**)&yhi, g_yhi);
    cudaGetSymbolAddress((void**)&ylo, g_ylo);

    const int gemm_smem = 2 * STAGE_B;  // 81920
    cudaFuncSetAttribute(gemm_mma,
                         cudaFuncAttributeMaxDynamicSharedMemorySize, gemm_smem);
    const int attn_smem = (64 * 132 + 64 * 68 + 64 * 68 + 128 * 68) * 4;
    cudaFuncSetAttribute(attn_kernel,
                         cudaFuncAttributeMaxDynamicSharedMemorySize, attn_smem);

    // 0) split conversions
    convert_split<<<4096, 256>>>(x, xhi, xlo);
    transpose_split<<<dim3(96, 32), dim3(32, 8)>>>(Wqkv, wqh, wql, 1024, 3072);
    transpose_split<<<dim3(32, 32), dim3(32, 8)>>>(Wproj, wph, wpl, 1024, 1024);

    // 1) QKV GEMM [4096,1024]x[1024,3072] (tensor cores, split bf16)
    gemm_mma<<<dim3(24, 32), 256, gemm_smem>>>(
        xhi, xlo, wqh, wql, bqkv, qkv, 4096, 3072, 1024);

    // 2) RoPE + scatter
    rope_scatter<<<8192, 256>>>(qkv, cs, sn, qheads, out_k, out_v);

    // 3) Attention (fp32)
    attn_kernel<<<dim3(2048 / 128, 2 * 16), 256, attn_smem>>>(
        qheads, out_k, out_v, ybuf);

    // 4) Projection [4096,1024]x[1024,1024]
    convert_split<<<4096, 256>>>(ybuf, yhi, ylo);
    gemm_mma<<<dim3(8, 32), 256, gemm_smem>>>(
        yhi, ylo, wph, wpl, bproj, out_y, 4096, 1024, 1024);
}

// round 6
// speedup vs baseline: 2.8677x; 1.8242x over previous
#include <cuda_runtime.h>
#include <cuda_bf16.h>
#include <math.h>
#include <stdint.h>

// B=2, S=2048, D=1024, H=16, HD=64

// ---------------- scratch (device globals) ----------------
__device__ float g_qkv[(size_t)2 * 2048 * 3072];               // [B*S, 3D]

__device__ __nv_bfloat16 g_xhi[4194304], g_xlo[4194304];       // x split
__device__ __nv_bfloat16 g_wqt_hi[3145728], g_wqt_lo[3145728]; // Wqkv^T split
__device__ __nv_bfloat16 g_wpt_hi[1048576], g_wpt_lo[1048576]; // Wproj^T split
__device__ __nv_bfloat16 g_yhi[4194304], g_ylo[4194304];       // attn out split

__device__ __nv_bfloat16 g_qh[4194304], g_ql[4194304];         // q heads split
__device__ __nv_bfloat16 g_kh[4194304], g_kl[4194304];         // k heads split
__device__ __nv_bfloat16 g_vh[4194304], g_vl[4194304];         // v heads split

// ---------------- helpers ----------------
__device__ __forceinline__ uint32_t smem_u32(const void* p) {
    uint32_t a;
    asm("{ .reg .u64 t; cvta.to.shared.u64 t, %1; cvt.u32.u64 %0, t; }"
        : "=r"(a) : "l"(p));
    return a;
}

#define CP_ASYNC16(dst, src) \
    asm volatile("cp.async.cg.shared.global [%0], [%1], 16;" \
                 :: "r"(dst), "l"(src))
#define CP_COMMIT() asm volatile("cp.async.commit_group;" ::: "memory")
#define CP_WAIT(n)  asm volatile("cp.async.wait_group %0;" :: "n"(n) : "memory")

__device__ __forceinline__ void ldmx4(uint32_t* r, uint32_t addr) {
    asm volatile("ldmatrix.sync.aligned.m8n8.x4.shared.b16 {%0,%1,%2,%3}, [%4];"
                 : "=r"(r[0]), "=r"(r[1]), "=r"(r[2]), "=r"(r[3]) : "r"(addr));
}
__device__ __forceinline__ void ldmx4t(uint32_t* r, uint32_t addr) {
    asm volatile("ldmatrix.sync.aligned.m8n8.x4.trans.shared.b16 {%0,%1,%2,%3}, [%4];"
                 : "=r"(r[0]), "=r"(r[1]), "=r"(r[2]), "=r"(r[3]) : "r"(addr));
}
__device__ __forceinline__ void mma16816(float* d, const uint32_t* a,
                                         const uint32_t* b) {
    asm volatile(
        "mma.sync.aligned.m16n8k16.row.col.f32.bf16.bf16.f32 "
        "{%0,%1,%2,%3}, {%4,%5,%6,%7}, {%8,%9}, {%0,%1,%2,%3};"
        : "+f"(d[0]), "+f"(d[1]), "+f"(d[2]), "+f"(d[3])
        : "r"(a[0]), "r"(a[1]), "r"(a[2]), "r"(a[3]), "r"(b[0]), "r"(b[1]));
}

__device__ __forceinline__ void psplit(float a, float b,
                                       uint32_t& hi, uint32_t& lo) {
    __nv_bfloat16 ha = __float2bfloat16(a), hb = __float2bfloat16(b);
    __nv_bfloat16 la = __float2bfloat16(a - __bfloat162float(ha));
    __nv_bfloat16 lb = __float2bfloat16(b - __bfloat162float(hb));
    __nv_bfloat162 h2 = __halves2bfloat162(ha, hb);
    __nv_bfloat162 l2 = __halves2bfloat162(la, lb);
    hi = *reinterpret_cast<uint32_t*>(&h2);
    lo = *reinterpret_cast<uint32_t*>(&l2);
}

__device__ __forceinline__ void wsplit(__nv_bfloat16* hi, __nv_bfloat16* lo,
                                       size_t o, float a, float b) {
    __nv_bfloat16 ha = __float2bfloat16(a), hb = __float2bfloat16(b);
    __nv_bfloat16 la = __float2bfloat16(a - __bfloat162float(ha));
    __nv_bfloat16 lb = __float2bfloat16(b - __bfloat162float(hb));
    *reinterpret_cast<__nv_bfloat162*>(hi + o) = __halves2bfloat162(ha, hb);
    *reinterpret_cast<__nv_bfloat162*>(lo + o) = __halves2bfloat162(la, lb);
}

// ---------------------------------------------------------------------------
// Split-precision conversion kernels
// ---------------------------------------------------------------------------
__global__ __launch_bounds__(256) void convert_split(
    const float* __restrict__ in, __nv_bfloat16* __restrict__ hi,
    __nv_bfloat16* __restrict__ lo)
{
    int i = (blockIdx.x * blockDim.x + threadIdx.x) << 2;
    float4 v = *(const float4*)(in + i);
    wsplit(hi, lo, i, v.x, v.y);
    wsplit(hi, lo, i + 2, v.z, v.w);
}

// W[K][N] f32 -> Wt_hi/lo[N][K] bf16 (transpose + split)
__global__ __launch_bounds__(256) void transpose_split(
    const float* __restrict__ W, __nv_bfloat16* __restrict__ Thi,
    __nv_bfloat16* __restrict__ Tlo, int K, int N)
{
    __shared__ float t[32][33];
    int n0 = blockIdx.x << 5, k0 = blockIdx.y << 5;
    int tx = threadIdx.x, ty = threadIdx.y;   // 32 x 8
    #pragma unroll
    for (int i = 0; i < 4; i++)
        t[ty + 8 * i][tx] = W[(size_t)(k0 + ty + 8 * i) * N + n0 + tx];
    __syncthreads();
    #pragma unroll
    for (int i = 0; i < 4; i++) {
        float v = t[tx][ty + 8 * i];
        __nv_bfloat16 h = __float2bfloat16(v);
        __nv_bfloat16 l = __float2bfloat16(v - __bfloat162float(h));
        size_t o = (size_t)(n0 + ty + 8 * i) * K + k0 + tx;
        Thi[o] = h;
        Tlo[o] = l;
    }
}

// ---------------------------------------------------------------------------
// Split-bf16 GEMM via mma.sync (unchanged from round 5)
// ---------------------------------------------------------------------------
#define TILE_B 10240
#define STAGE_B 40960

__device__ __forceinline__ void gemm_load_chunk(
    uint32_t sst,
    const __nv_bfloat16* __restrict__ Ahi, const __nv_bfloat16* __restrict__ Alo,
    const __nv_bfloat16* __restrict__ Bhi, const __nv_bfloat16* __restrict__ Blo,
    int bm, int bn, int K, int k0, int tid)
{
    #pragma unroll
    for (int j = 0; j < 2; j++) {
        int u = tid + (j << 8);
        int r = u >> 2;
        int c16 = (u & 3) << 4;
        uint32_t d = sst + (uint32_t)r * 80 + c16;
        size_t ga = ((size_t)(bm + r) * K + k0) * 2 + c16;
        size_t gb = ((size_t)(bn + r) * K + k0) * 2 + c16;
        CP_ASYNC16(d,               (const char*)Ahi + ga);
        CP_ASYNC16(d + TILE_B,      (const char*)Alo + ga);
        CP_ASYNC16(d + 2 * TILE_B,  (const char*)Bhi + gb);
        CP_ASYNC16(d + 3 * TILE_B,  (const char*)Blo + gb);
    }
}

__global__ __launch_bounds__(256) void gemm_mma(
    const __nv_bfloat16* __restrict__ Ahi, const __nv_bfloat16* __restrict__ Alo,
    const __nv_bfloat16* __restrict__ Bhi, const __nv_bfloat16* __restrict__ Blo,
    const float* __restrict__ bias, float* __restrict__ C,
    int M, int N, int K)
{
    extern __shared__ char smem[];
    const uint32_t sb = smem_u32(smem);

    const int tid = threadIdx.x;
    const int wid = tid >> 5;
    const int lane = tid & 31;
    const int bm = blockIdx.y << 7, bn = blockIdx.x << 7;
    const int wm = (wid >> 2) << 6;
    const int wn = (wid & 3) << 5;

    float acc[4][4][4] = {};

    gemm_load_chunk(sb, Ahi, Alo, Bhi, Blo, bm, bn, K, 0, tid);
    CP_COMMIT();

    const int nchunk = K >> 5;
    for (int c = 0; c < nchunk; c++) {
        const uint32_t st = sb + (uint32_t)(c & 1) * STAGE_B;
        if (c + 1 < nchunk) {
            gemm_load_chunk(sb + (uint32_t)((c + 1) & 1) * STAGE_B,
                            Ahi, Alo, Bhi, Blo, bm, bn, K, (c + 1) << 5, tid);
            CP_COMMIT();
            CP_WAIT(1);
        } else {
            CP_WAIT(0);
        }
        __syncthreads();

        #pragma unroll
        for (int ks = 0; ks < 2; ks++) {
            const int kb = ks << 5;
            uint32_t af[2][4][4];
            #pragma unroll
            for (int s = 0; s < 2; s++) {
                uint32_t abase = st + (uint32_t)s * TILE_B;
                #pragma unroll
                for (int mt = 0; mt < 4; mt++) {
                    uint32_t addr = abase
                        + (uint32_t)(wm + (mt << 4) + (lane & 15)) * 80
                        + kb + ((lane >> 4) << 4);
                    ldmx4(af[s][mt], addr);
                }
            }
            uint32_t bf[2][8];
            #pragma unroll
            for (int s = 0; s < 2; s++) {
                uint32_t bbase = st + (uint32_t)(2 + s) * TILE_B;
                #pragma unroll
                for (int g = 0; g < 2; g++) {
                    uint32_t nrow = wn + (g << 4) + (((lane >> 4) & 1) << 3)
                                  + (lane & 7);
                    uint32_t addr = bbase + nrow * 80 + kb
                                  + (((lane >> 3) & 1) << 4);
                    ldmx4(&bf[s][g << 2], addr);
                }
            }
            #pragma unroll
            for (int mt = 0; mt < 4; mt++)
                #pragma unroll
                for (int nt = 0; nt < 4; nt++) {
                    mma16816(acc[mt][nt], af[0][mt], &bf[0][nt << 1]);
                    mma16816(acc[mt][nt], af[0][mt], &bf[1][nt << 1]);
                    mma16816(acc[mt][nt], af[1][mt], &bf[0][nt << 1]);
                }
        }
        __syncthreads();
    }

    const int r0 = bm + wm + (lane >> 2);
    const int cc0 = bn + wn + ((lane & 3) << 1);
    #pragma unroll
    for (int mt = 0; mt < 4; mt++) {
        #pragma unroll
        for (int nt = 0; nt < 4; nt++) {
            int col = cc0 + (nt << 3);
            float b0 = bias[col], b1 = bias[col + 1];
            int ra = r0 + (mt << 4);
            float2 v0 = make_float2(acc[mt][nt][0] + b0, acc[mt][nt][1] + b1);
            float2 v1 = make_float2(acc[mt][nt][2] + b0, acc[mt][nt][3] + b1);
            *(float2*)&C[(size_t)ra * N + col] = v0;
            *(float2*)&C[(size_t)(ra + 8) * N + col] = v1;
        }
    }
}

// ---------------------------------------------------------------------------
// RoPE + head scatter. Writes k,v f32 (output) + split bf16 q(scaled)/k/v.
// ---------------------------------------------------------------------------
__global__ __launch_bounds__(256) void rope_scatter(
    const float* __restrict__ qkv,
    const float* __restrict__ cs, const float* __restrict__ sn,
    float* __restrict__ kout, float* __restrict__ vout,
    __nv_bfloat16* __restrict__ qh, __nv_bfloat16* __restrict__ ql,
    __nv_bfloat16* __restrict__ kh, __nv_bfloat16* __restrict__ kl,
    __nv_bfloat16* __restrict__ vh, __nv_bfloat16* __restrict__ vl)
{
    int idx = blockIdx.x * blockDim.x + threadIdx.x;
    int p = idx & 31;
    int h = (idx >> 5) & 15;
    int s = (idx >> 9) & 2047;
    int b = idx >> 20;

    const float* base = qkv + ((size_t)(b * 2048 + s)) * 3072 + h * 64 + 2 * p;
    float c0 = cs[s * 64 + 2 * p], c1 = cs[s * 64 + 2 * p + 1];
    float s0 = sn[s * 64 + 2 * p], s1 = sn[s * 64 + 2 * p + 1];

    float q0 = base[0],    q1 = base[1];
    float k0 = base[1024], k1 = base[1025];
    float v0 = base[2048], v1 = base[2049];

    float rq0 = (q0 * c0 - q1 * s0) * 0.125f;
    float rq1 = (q1 * c1 + q0 * s1) * 0.125f;
    float rk0 = k0 * c0 - k1 * s0;
    float rk1 = k1 * c1 + k0 * s1;

    size_t o = (((size_t)(b * 16 + h)) * 2048 + s) * 64 + 2 * p;
    kout[o] = rk0; kout[o + 1] = rk1;
    vout[o] = v0;  vout[o + 1] = v1;
    wsplit(qh, ql, o, rq0, rq1);
    wsplit(kh, kl, o, rk0, rk1);
    wsplit(vh, vl, o, v0, v1);
}

// ---------------------------------------------------------------------------
// Flash attention via mma.sync, split bf16, online softmax in registers.
// CTA = 128 q-rows of one (b,h); 8 warps x 16 rows; 32 kv tiles of 64.
// ---------------------------------------------------------------------------
#define AST 144               // smem row stride (bytes), 9x16B -> LDSM conflict-free
#define ASTG 36864            // stage: khi,klo,vhi,vlo @ 64*144 each

__global__ __launch_bounds__(256) void attn_mma(
    const __nv_bfloat16* __restrict__ qhi, const __nv_bfloat16* __restrict__ qlo,
    const __nv_bfloat16* __restrict__ khi, const __nv_bfloat16* __restrict__ klo,
    const __nv_bfloat16* __restrict__ vhi, const __nv_bfloat16* __restrict__ vlo,
    __nv_bfloat16* __restrict__ yhi, __nv_bfloat16* __restrict__ ylo)
{
    extern __shared__ char smx[];
    const uint32_t sb = smem_u32(smx);
    const int tid = threadIdx.x, wid = tid >> 5, lane = tid & 31;
    const int bh = blockIdx.y, q0 = blockIdx.x << 7;
    const uint32_t QH = sb + ASTG, QL = QH + 18432;   // Q staging (= stage 1)

    const size_t hbase = (size_t)bh * 2048 * 64;
    const char* kh = (const char*)(khi + hbase);
    const char* kl = (const char*)(klo + hbase);
    const char* vh = (const char*)(vhi + hbase);
    const char* vl = (const char*)(vlo + hbase);

    // Q -> smem (group 0)
    {
        const char* qhg = (const char*)(qhi + hbase + (size_t)q0 * 64);
        const char* qlg = (const char*)(qlo + hbase + (size_t)q0 * 64);
        #pragma unroll
        for (int j = 0; j < 4; j++) {
            int u = tid + (j << 8); int r = u >> 3; int c = (u & 7) << 4;
            CP_ASYNC16(QH + r * AST + c, qhg + r * 128 + c);
            CP_ASYNC16(QL + r * AST + c, qlg + r * 128 + c);
        }
        CP_COMMIT();
    }
    // tile 0 -> stage 0 (group 1)
    {
        #pragma unroll
        for (int j = 0; j < 2; j++) {
            int u = tid + (j << 8); int r = u >> 3; int c = (u & 7) << 4;
            uint32_t d = sb + r * AST + c;
            int go = r * 128 + c;
            CP_ASYNC16(d, kh + go);         CP_ASYNC16(d + 9216, kl + go);
            CP_ASYNC16(d + 18432, vh + go); CP_ASYNC16(d + 27648, vl + go);
        }
        CP_COMMIT();
    }
    CP_WAIT(1);
    __syncthreads();

    // Q fragments (kept in registers for the whole kernel)
    uint32_t qfh[4][4], qfl[4][4];
    #pragma unroll
    for (int kt = 0; kt < 4; kt++) {
        uint32_t a = QH + (uint32_t)((wid << 4) + (lane & 15)) * AST
                   + (kt << 5) + ((lane >> 4) << 4);
        ldmx4(qfh[kt], a);
        ldmx4(qfl[kt], a + 18432);
    }
    __syncthreads();   // Q region now reusable as stage 1

    float m0 = -1e30f, m1 = -1e30f, l0 = 0.f, l1 = 0.f;
    float o[8][4] = {};

    for (int t = 0; t < 32; t++) {
        const uint32_t st = sb + (uint32_t)(t & 1) * ASTG;
        if (t + 1 < 32) {
            uint32_t dstg = sb + (uint32_t)((t + 1) & 1) * ASTG;
            size_t tb = (size_t)(t + 1) * 64 * 128;
            #pragma unroll
            for (int j = 0; j < 2; j++) {
                int u = tid + (j << 8); int r = u >> 3; int c = (u & 7) << 4;
                uint32_t d = dstg + r * AST + c;
                size_t go = tb + r * 128 + c;
                CP_ASYNC16(d, kh + go);         CP_ASYNC16(d + 9216, kl + go);
                CP_ASYNC16(d + 18432, vh + go); CP_ASYNC16(d + 27648, vl + go);
            }
            CP_COMMIT();
            CP_WAIT(1);
        } else {
            CP_WAIT(0);
        }
        __syncthreads();

        // S = Q K^T (3-pass split)
        float sacc[8][4] = {};
        #pragma unroll
        for (int kt = 0; kt < 4; kt++) {
            #pragma unroll
            for (int g = 0; g < 4; g++) {
                uint32_t na = st
                    + (uint32_t)((g << 4) + (((lane >> 4) & 1) << 3) + (lane & 7)) * AST
                    + (kt << 5) + (((lane >> 3) & 1) << 4);
                uint32_t kfh[4], kfl[4];
                ldmx4(kfh, na);
                ldmx4(kfl, na + 9216);
                mma16816(sacc[2 * g],     qfh[kt], &kfh[0]);
                mma16816(sacc[2 * g],     qfh[kt], &kfl[0]);
                mma16816(sacc[2 * g],     qfl[kt], &kfh[0]);
                mma16816(sacc[2 * g + 1], qfh[kt], &kfh[2]);
                mma16816(sacc[2 * g + 1], qfh[kt], &kfl[2]);
                mma16816(sacc[2 * g + 1], qfl[kt], &kfh[2]);
            }
        }

        // online softmax (rows r0 = lane/4, r1 = r0+8; cols across lane%4)
        float mx0 = -1e30f, mx1 = -1e30f;
        #pragma unroll
        for (int n = 0; n < 8; n++) {
            mx0 = fmaxf(mx0, fmaxf(sacc[n][0], sacc[n][1]));
            mx1 = fmaxf(mx1, fmaxf(sacc[n][2], sacc[n][3]));
        }
        mx0 = fmaxf(mx0, __shfl_xor_sync(0xffffffffu, mx0, 1));
        mx0 = fmaxf(mx0, __shfl_xor_sync(0xffffffffu, mx0, 2));
        mx1 = fmaxf(mx1, __shfl_xor_sync(0xffffffffu, mx1, 1));
        mx1 = fmaxf(mx1, __shfl_xor_sync(0xffffffffu, mx1, 2));
        float nm0 = fmaxf(m0, mx0), nm1 = fmaxf(m1, mx1);
        float al0 = __expf(m0 - nm0), al1 = __expf(m1 - nm1);
        float rs0 = 0.f, rs1 = 0.f;
        #pragma unroll
        for (int n = 0; n < 8; n++) {
            sacc[n][0] = __expf(sacc[n][0] - nm0);
            sacc[n][1] = __expf(sacc[n][1] - nm0);
            sacc[n][2] = __expf(sacc[n][2] - nm1);
            sacc[n][3] = __expf(sacc[n][3] - nm1);
            rs0 += sacc[n][0] + sacc[n][1];
            rs1 += sacc[n][2] + sacc[n][3];
        }
        rs0 += __shfl_xor_sync(0xffffffffu, rs0, 1);
        rs0 += __shfl_xor_sync(0xffffffffu, rs0, 2);
        rs1 += __shfl_xor_sync(0xffffffffu, rs1, 1);
        rs1 += __shfl_xor_sync(0xffffffffu, rs1, 2);
        l0 = l0 * al0 + rs0; l1 = l1 * al1 + rs1;
        m0 = nm0; m1 = nm1;
        #pragma unroll
        for (int n = 0; n < 8; n++) {
            o[n][0] *= al0; o[n][1] *= al0;
            o[n][2] *= al1; o[n][3] *= al1;
        }

        // O += P V (P split in registers; V frags via ldmatrix.trans)
        #pragma unroll
        for (int kt = 0; kt < 4; kt++) {
            uint32_t ph[4], pl[4];
            psplit(sacc[2 * kt][0],     sacc[2 * kt][1],     ph[0], pl[0]);
            psplit(sacc[2 * kt][2],     sacc[2 * kt][3],     ph[1], pl[1]);
            psplit(sacc[2 * kt + 1][0], sacc[2 * kt + 1][1], ph[2], pl[2]);
            psplit(sacc[2 * kt + 1][2], sacc[2 * kt + 1][3], ph[3], pl[3]);
            #pragma unroll
            for (int g = 0; g < 4; g++) {
                uint32_t va = st + 18432
                    + (uint32_t)((kt << 4) + (lane & 7) + (((lane >> 3) & 1) << 3)) * AST
                    + (((g << 4) + (((lane >> 4) & 1) << 3)) << 1);
                uint32_t vfh[4], vfl[4];
                ldmx4t(vfh, va);
                ldmx4t(vfl, va + 9216);
                mma16816(o[2 * g],     ph, &vfh[0]);
                mma16816(o[2 * g],     ph, &vfl[0]);
                mma16816(o[2 * g],     pl, &vfh[0]);
                mma16816(o[2 * g + 1], ph, &vfh[2]);
                mma16816(o[2 * g + 1], ph, &vfl[2]);
                mma16816(o[2 * g + 1], pl, &vfh[2]);
            }
        }
        __syncthreads();   // compute done before next iter overwrites stage
    }

    // epilogue: y = O / l, written as bf16 hi/lo splits (proj input)
    float il0 = 1.f / l0, il1 = 1.f / l1;
    const int b = bh >> 4, h = bh & 15;
    const int r0 = b * 2048 + q0 + (wid << 4) + (lane >> 2);
    const int c0 = h * 64 + ((lane & 3) << 1);
    #pragma unroll
    for (int n = 0; n < 8; n++) {
        size_t o0 = (size_t)r0 * 1024 + c0 + (n << 3);
        wsplit(yhi, ylo, o0, o[n][0] * il0, o[n][1] * il0);
        wsplit(yhi, ylo, o0 + 8 * 1024, o[n][2] * il1, o[n][3] * il1);
    }
}

// ---------------------------------------------------------------------------
extern "C" void kernel_launch(void* const* d_in, const int* in_sizes, int n_in,
                              void* d_out, int out_size)
{
    const float* x     = (const float*)d_in[0];
    const float* cs    = (const float*)d_in[1];
    const float* sn    = (const float*)d_in[2];
    const float* Wqkv  = (const float*)d_in[3];
    const float* bqkv  = (const float*)d_in[4];
    const float* Wproj = (const float*)d_in[5];
    const float* bproj = (const float*)d_in[6];

    float* out   = (float*)d_out;
    float* out_y = out;
    float* out_k = out + (size_t)2 * 2048 * 1024;
    float* out_v = out_k + (size_t)2 * 16 * 2048 * 64;

    float* qkv;
    cudaGetSymbolAddress((void**)&qkv, g_qkv);
    __nv_bfloat16 *xhi, *xlo, *wqh, *wql, *wph, *wpl, *yhi, *ylo;
    __nv_bfloat16 *qh, *ql, *kh, *kl, *vh, *vl;
    cudaGetSymbolAddress((void**)&xhi, g_xhi);
    cudaGetSymbolAddress((void**)&xlo, g_xlo);
    cudaGetSymbolAddress((void**)&wqh, g_wqt_hi);
    cudaGetSymbolAddress((void**)&wql, g_wqt_lo);
    cudaGetSymbolAddress((void**)&wph, g_wpt_hi);
    cudaGetSymbolAddress((void**)&wpl, g_wpt_lo);
    cudaGetSymbolAddress((void**)&yhi, g_yhi);
    cudaGetSymbolAddress((void**)&ylo, g_ylo);
    cudaGetSymbolAddress((void**)&qh, g_qh);
    cudaGetSymbolAddress((void**)&ql, g_ql);
    cudaGetSymbolAddress((void**)&kh, g_kh);
    cudaGetSymbolAddress((void**)&kl, g_kl);
    cudaGetSymbolAddress((void**)&vh, g_vh);
    cudaGetSymbolAddress((void**)&vl, g_vl);

    const int gemm_smem = 2 * STAGE_B;
    cudaFuncSetAttribute(gemm_mma,
                         cudaFuncAttributeMaxDynamicSharedMemorySize, gemm_smem);
    const int attn_smem = 2 * ASTG;   // 73728
    cudaFuncSetAttribute(attn_mma,
                         cudaFuncAttributeMaxDynamicSharedMemorySize, attn_smem);

    // 0) split conversions
    convert_split<<<4096, 256>>>(x, xhi, xlo);
    transpose_split<<<dim3(96, 32), dim3(32, 8)>>>(Wqkv, wqh, wql, 1024, 3072);
    transpose_split<<<dim3(32, 32), dim3(32, 8)>>>(Wproj, wph, wpl, 1024, 1024);

    // 1) QKV GEMM (tensor cores, split bf16)
    gemm_mma<<<dim3(24, 32), 256, gemm_smem>>>(
        xhi, xlo, wqh, wql, bqkv, qkv, 4096, 3072, 1024);

    // 2) RoPE + scatter (+ split bf16 heads)
    rope_scatter<<<8192, 256>>>(qkv, cs, sn, out_k, out_v,
                                qh, ql, kh, kl, vh, vl);

    // 3) Attention (tensor cores, split bf16) -> y splits
    attn_mma<<<dim3(16, 32), 256, attn_smem>>>(
        qh, ql, kh, kl, vh, vl, yhi, ylo);

    // 4) Projection (tensor cores, split bf16)
    gemm_mma<<<dim3(8, 32), 256, gemm_smem>>>(
        yhi, ylo, wph, wpl, bproj, out_y, 4096, 1024, 1024);
}

// round 7
// speedup vs baseline: 2.8800x; 1.0043x over previous
#include <cuda_runtime.h>
#include <cuda_bf16.h>
#include <math.h>
#include <stdint.h>

// B=2, S=2048, D=1024, H=16, HD=64

// ---------------- scratch (device globals) ----------------
__device__ __nv_bfloat16 g_xhi[4194304], g_xlo[4194304];       // x split
__device__ __nv_bfloat16 g_wqt_hi[3145728], g_wqt_lo[3145728]; // Wqkv^T split
__device__ __nv_bfloat16 g_wpt_hi[1048576], g_wpt_lo[1048576]; // Wproj^T split
__device__ __nv_bfloat16 g_yhi[4194304], g_ylo[4194304];       // attn out split

__device__ __nv_bfloat16 g_qh[4194304], g_ql[4194304];         // q heads split
__device__ __nv_bfloat16 g_kh[4194304], g_kl[4194304];         // k heads split
__device__ __nv_bfloat16 g_vh[4194304], g_vl[4194304];         // v heads split

// ---------------- helpers ----------------
__device__ __forceinline__ uint32_t smem_u32(const void* p) {
    uint32_t a;
    asm("{ .reg .u64 t; cvta.to.shared.u64 t, %1; cvt.u32.u64 %0, t; }"
        : "=r"(a) : "l"(p));
    return a;
}

#define CP_ASYNC16(dst, src) \
    asm volatile("cp.async.cg.shared.global [%0], [%1], 16;" \
                 :: "r"(dst), "l"(src))
#define CP_COMMIT() asm volatile("cp.async.commit_group;" ::: "memory")
#define CP_WAIT(n)  asm volatile("cp.async.wait_group %0;" :: "n"(n) : "memory")

__device__ __forceinline__ void ldmx4(uint32_t* r, uint32_t addr) {
    asm volatile("ldmatrix.sync.aligned.m8n8.x4.shared.b16 {%0,%1,%2,%3}, [%4];"
                 : "=r"(r[0]), "=r"(r[1]), "=r"(r[2]), "=r"(r[3]) : "r"(addr));
}
__device__ __forceinline__ void ldmx4t(uint32_t* r, uint32_t addr) {
    asm volatile("ldmatrix.sync.aligned.m8n8.x4.trans.shared.b16 {%0,%1,%2,%3}, [%4];"
                 : "=r"(r[0]), "=r"(r[1]), "=r"(r[2]), "=r"(r[3]) : "r"(addr));
}
__device__ __forceinline__ void mma16816(float* d, const uint32_t* a,
                                         const uint32_t* b) {
    asm volatile(
        "mma.sync.aligned.m16n8k16.row.col.f32.bf16.bf16.f32 "
        "{%0,%1,%2,%3}, {%4,%5,%6,%7}, {%8,%9}, {%0,%1,%2,%3};"
        : "+f"(d[0]), "+f"(d[1]), "+f"(d[2]), "+f"(d[3])
        : "r"(a[0]), "r"(a[1]), "r"(a[2]), "r"(a[3]), "r"(b[0]), "r"(b[1]));
}

__device__ __forceinline__ void psplit(float a, float b,
                                       uint32_t& hi, uint32_t& lo) {
    __nv_bfloat16 ha = __float2bfloat16(a), hb = __float2bfloat16(b);
    __nv_bfloat16 la = __float2bfloat16(a - __bfloat162float(ha));
    __nv_bfloat16 lb = __float2bfloat16(b - __bfloat162float(hb));
    __nv_bfloat162 h2 = __halves2bfloat162(ha, hb);
    __nv_bfloat162 l2 = __halves2bfloat162(la, lb);
    hi = *reinterpret_cast<uint32_t*>(&h2);
    lo = *reinterpret_cast<uint32_t*>(&l2);
}

__device__ __forceinline__ void wsplit(__nv_bfloat16* hi, __nv_bfloat16* lo,
                                       size_t o, float a, float b) {
    __nv_bfloat16 ha = __float2bfloat16(a), hb = __float2bfloat16(b);
    __nv_bfloat16 la = __float2bfloat16(a - __bfloat162float(ha));
    __nv_bfloat16 lb = __float2bfloat16(b - __bfloat162float(hb));
    *reinterpret_cast<__nv_bfloat162*>(hi + o) = __halves2bfloat162(ha, hb);
    *reinterpret_cast<__nv_bfloat162*>(lo + o) = __halves2bfloat162(la, lb);
}

// ---------------------------------------------------------------------------
// Split-precision conversion kernels
// ---------------------------------------------------------------------------
__global__ __launch_bounds__(256) void convert_split(
    const float* __restrict__ in, __nv_bfloat16* __restrict__ hi,
    __nv_bfloat16* __restrict__ lo)
{
    int i = (blockIdx.x * blockDim.x + threadIdx.x) << 2;
    float4 v = *(const float4*)(in + i);
    wsplit(hi, lo, i, v.x, v.y);
    wsplit(hi, lo, i + 2, v.z, v.w);
}

// W[K][N] f32 -> Wt_hi/lo[N][K] bf16 (transpose + split)
__global__ __launch_bounds__(256) void transpose_split(
    const float* __restrict__ W, __nv_bfloat16* __restrict__ Thi,
    __nv_bfloat16* __restrict__ Tlo, int K, int N)
{
    __shared__ float t[32][33];
    int n0 = blockIdx.x << 5, k0 = blockIdx.y << 5;
    int tx = threadIdx.x, ty = threadIdx.y;   // 32 x 8
    #pragma unroll
    for (int i = 0; i < 4; i++)
        t[ty + 8 * i][tx] = W[(size_t)(k0 + ty + 8 * i) * N + n0 + tx];
    __syncthreads();
    #pragma unroll
    for (int i = 0; i < 4; i++) {
        float v = t[tx][ty + 8 * i];
        __nv_bfloat16 h = __float2bfloat16(v);
        __nv_bfloat16 l = __float2bfloat16(v - __bfloat162float(h));
        size_t o = (size_t)(n0 + ty + 8 * i) * K + k0 + tx;
        Thi[o] = h;
        Tlo[o] = l;
    }
}

// ---------------------------------------------------------------------------
// Split-bf16 GEMM via mma.sync. QKV variant fuses bias+RoPE+scatter+split.
// ---------------------------------------------------------------------------
#define TILE_B 10240
#define STAGE_B 40960

__device__ __forceinline__ void gemm_load_chunk(
    uint32_t sst,
    const __nv_bfloat16* __restrict__ Ahi, const __nv_bfloat16* __restrict__ Alo,
    const __nv_bfloat16* __restrict__ Bhi, const __nv_bfloat16* __restrict__ Blo,
    int bm, int bn, int K, int k0, int tid)
{
    #pragma unroll
    for (int j = 0; j < 2; j++) {
        int u = tid + (j << 8);
        int r = u >> 2;
        int c16 = (u & 3) << 4;
        uint32_t d = sst + (uint32_t)r * 80 + c16;
        size_t ga = ((size_t)(bm + r) * K + k0) * 2 + c16;
        size_t gb = ((size_t)(bn + r) * K + k0) * 2 + c16;
        CP_ASYNC16(d,               (const char*)Ahi + ga);
        CP_ASYNC16(d + TILE_B,      (const char*)Alo + ga);
        CP_ASYNC16(d + 2 * TILE_B,  (const char*)Bhi + gb);
        CP_ASYNC16(d + 3 * TILE_B,  (const char*)Blo + gb);
    }
}

template<bool QKV>
__global__ __launch_bounds__(256) void gemm_mma(
    const __nv_bfloat16* __restrict__ Ahi, const __nv_bfloat16* __restrict__ Alo,
    const __nv_bfloat16* __restrict__ Bhi, const __nv_bfloat16* __restrict__ Blo,
    const float* __restrict__ bias, float* __restrict__ C,
    int M, int N, int K,
    // QKV epilogue extras
    const float* __restrict__ cs, const float* __restrict__ sn,
    float* __restrict__ out_k, float* __restrict__ out_v,
    __nv_bfloat16* __restrict__ qhx, __nv_bfloat16* __restrict__ qlx,
    __nv_bfloat16* __restrict__ khx, __nv_bfloat16* __restrict__ klx,
    __nv_bfloat16* __restrict__ vhx, __nv_bfloat16* __restrict__ vlx)
{
    extern __shared__ char smem[];
    const uint32_t sb = smem_u32(smem);

    const int tid = threadIdx.x;
    const int wid = tid >> 5;
    const int lane = tid & 31;
    const int bm = blockIdx.y << 7, bn = blockIdx.x << 7;
    const int wm = (wid >> 2) << 6;
    const int wn = (wid & 3) << 5;

    float acc[4][4][4] = {};

    gemm_load_chunk(sb, Ahi, Alo, Bhi, Blo, bm, bn, K, 0, tid);
    CP_COMMIT();

    const int nchunk = K >> 5;
    for (int c = 0; c < nchunk; c++) {
        const uint32_t st = sb + (uint32_t)(c & 1) * STAGE_B;
        if (c + 1 < nchunk) {
            gemm_load_chunk(sb + (uint32_t)((c + 1) & 1) * STAGE_B,
                            Ahi, Alo, Bhi, Blo, bm, bn, K, (c + 1) << 5, tid);
            CP_COMMIT();
            CP_WAIT(1);
        } else {
            CP_WAIT(0);
        }
        __syncthreads();

        #pragma unroll
        for (int ks = 0; ks < 2; ks++) {
            const int kb = ks << 5;
            uint32_t af[2][4][4];
            #pragma unroll
            for (int s = 0; s < 2; s++) {
                uint32_t abase = st + (uint32_t)s * TILE_B;
                #pragma unroll
                for (int mt = 0; mt < 4; mt++) {
                    uint32_t addr = abase
                        + (uint32_t)(wm + (mt << 4) + (lane & 15)) * 80
                        + kb + ((lane >> 4) << 4);
                    ldmx4(af[s][mt], addr);
                }
            }
            uint32_t bf[2][8];
            #pragma unroll
            for (int s = 0; s < 2; s++) {
                uint32_t bbase = st + (uint32_t)(2 + s) * TILE_B;
                #pragma unroll
                for (int g = 0; g < 2; g++) {
                    uint32_t nrow = wn + (g << 4) + (((lane >> 4) & 1) << 3)
                                  + (lane & 7);
                    uint32_t addr = bbase + nrow * 80 + kb
                                  + (((lane >> 3) & 1) << 4);
                    ldmx4(&bf[s][g << 2], addr);
                }
            }
            // pass-major: 16 independent accumulators between reuses
            #pragma unroll
            for (int p = 0; p < 3; p++) {
                const int sa = (p == 2) ? 1 : 0;
                const int sbb = (p == 1) ? 1 : 0;
                #pragma unroll
                for (int mt = 0; mt < 4; mt++)
                    #pragma unroll
                    for (int nt = 0; nt < 4; nt++)
                        mma16816(acc[mt][nt], af[sa][mt], &bf[sbb][nt << 1]);
            }
        }
        __syncthreads();
    }

    const int r0 = bm + wm + (lane >> 2);
    const int cc0 = bn + wn + ((lane & 3) << 1);

    if (!QKV) {
        #pragma unroll
        for (int mt = 0; mt < 4; mt++) {
            #pragma unroll
            for (int nt = 0; nt < 4; nt++) {
                int col = cc0 + (nt << 3);
                float b0 = bias[col], b1 = bias[col + 1];
                int ra = r0 + (mt << 4);
                float2 v0 = make_float2(acc[mt][nt][0] + b0, acc[mt][nt][1] + b1);
                float2 v1 = make_float2(acc[mt][nt][2] + b0, acc[mt][nt][3] + b1);
                *(float2*)&C[(size_t)ra * N + col] = v0;
                *(float2*)&C[(size_t)(ra + 8) * N + col] = v1;
            }
        }
    } else {
        // fused bias + RoPE + head scatter + hi/lo split
        const int region = bn >> 10;            // 0=q, 1=k, 2=v
        #pragma unroll
        for (int mt = 0; mt < 4; mt++) {
            #pragma unroll
            for (int rr = 0; rr < 2; rr++) {
                int row = r0 + (mt << 4) + (rr << 3);
                int s = row & 2047, bb = row >> 11;
                #pragma unroll
                for (int nt = 0; nt < 4; nt++) {
                    int col = cc0 + (nt << 3);
                    float2 bp = *(const float2*)&bias[col];
                    float v0 = acc[mt][nt][rr * 2]     + bp.x;
                    float v1 = acc[mt][nt][rr * 2 + 1] + bp.y;
                    int d = col - (region << 10);
                    int h = d >> 6, hd = d & 63;
                    size_t o = (((size_t)(bb * 16 + h)) * 2048 + s) * 64 + hd;
                    if (region == 2) {
                        wsplit(vhx, vlx, o, v0, v1);
                        *(float2*)&out_v[o] = make_float2(v0, v1);
                    } else {
                        float2 cp = *(const float2*)&cs[s * 64 + hd];
                        float2 sp = *(const float2*)&sn[s * 64 + hd];
                        float rv0 = v0 * cp.x - v1 * sp.x;
                        float rv1 = v1 * cp.y + v0 * sp.y;
                        if (region == 0) {
                            wsplit(qhx, qlx, o, rv0 * 0.125f, rv1 * 0.125f);
                        } else {
                            wsplit(khx, klx, o, rv0, rv1);
                            *(float2*)&out_k[o] = make_float2(rv0, rv1);
                        }
                    }
                }
            }
        }
    }
}

// ---------------------------------------------------------------------------
// Flash attention via mma.sync, split bf16, online softmax in registers.
// CTA = 128 q-rows of one (b,h); 8 warps x 16 rows; 32 kv tiles of 64.
// ---------------------------------------------------------------------------
#define AST 144               // smem row stride (bytes)
#define ASTG 36864            // stage: khi,klo,vhi,vlo @ 64*144 each

__global__ __launch_bounds__(256) void attn_mma(
    const __nv_bfloat16* __restrict__ qhi, const __nv_bfloat16* __restrict__ qlo,
    const __nv_bfloat16* __restrict__ khi, const __nv_bfloat16* __restrict__ klo,
    const __nv_bfloat16* __restrict__ vhi, const __nv_bfloat16* __restrict__ vlo,
    __nv_bfloat16* __restrict__ yhi, __nv_bfloat16* __restrict__ ylo)
{
    extern __shared__ char smx[];
    const uint32_t sb = smem_u32(smx);
    const int tid = threadIdx.x, wid = tid >> 5, lane = tid & 31;
    const int bh = blockIdx.y, q0 = blockIdx.x << 7;
    const uint32_t QH = sb + ASTG, QL = QH + 18432;   // Q staging (= stage 1)

    const size_t hbase = (size_t)bh * 2048 * 64;
    const char* kh = (const char*)(khi + hbase);
    const char* kl = (const char*)(klo + hbase);
    const char* vh = (const char*)(vhi + hbase);
    const char* vl = (const char*)(vlo + hbase);

    // Q -> smem (group 0)
    {
        const char* qhg = (const char*)(qhi + hbase + (size_t)q0 * 64);
        const char* qlg = (const char*)(qlo + hbase + (size_t)q0 * 64);
        #pragma unroll
        for (int j = 0; j < 4; j++) {
            int u = tid + (j << 8); int r = u >> 3; int c = (u & 7) << 4;
            CP_ASYNC16(QH + r * AST + c, qhg + r * 128 + c);
            CP_ASYNC16(QL + r * AST + c, qlg + r * 128 + c);
        }
        CP_COMMIT();
    }
    // tile 0 -> stage 0 (group 1)
    {
        #pragma unroll
        for (int j = 0; j < 2; j++) {
            int u = tid + (j << 8); int r = u >> 3; int c = (u & 7) << 4;
            uint32_t d = sb + r * AST + c;
            int go = r * 128 + c;
            CP_ASYNC16(d, kh + go);         CP_ASYNC16(d + 9216, kl + go);
            CP_ASYNC16(d + 18432, vh + go); CP_ASYNC16(d + 27648, vl + go);
        }
        CP_COMMIT();
    }
    CP_WAIT(1);
    __syncthreads();

    // Q fragments (registers for whole kernel)
    uint32_t qfh[4][4], qfl[4][4];
    #pragma unroll
    for (int kt = 0; kt < 4; kt++) {
        uint32_t a = QH + (uint32_t)((wid << 4) + (lane & 15)) * AST
                   + (kt << 5) + ((lane >> 4) << 4);
        ldmx4(qfh[kt], a);
        ldmx4(qfl[kt], a + 18432);
    }
    __syncthreads();   // Q region now reusable as stage 1

    float m0 = -1e30f, m1 = -1e30f, l0 = 0.f, l1 = 0.f;
    float o[8][4] = {};

    for (int t = 0; t < 32; t++) {
        const uint32_t st = sb + (uint32_t)(t & 1) * ASTG;
        if (t + 1 < 32) {
            uint32_t dstg = sb + (uint32_t)((t + 1) & 1) * ASTG;
            size_t tb = (size_t)(t + 1) * 64 * 128;
            #pragma unroll
            for (int j = 0; j < 2; j++) {
                int u = tid + (j << 8); int r = u >> 3; int c = (u & 7) << 4;
                uint32_t d = dstg + r * AST + c;
                size_t go = tb + r * 128 + c;
                CP_ASYNC16(d, kh + go);         CP_ASYNC16(d + 9216, kl + go);
                CP_ASYNC16(d + 18432, vh + go); CP_ASYNC16(d + 27648, vl + go);
            }
            CP_COMMIT();
            CP_WAIT(1);
        } else {
            CP_WAIT(0);
        }
        __syncthreads();

        // S = Q K^T, 3-pass split, pass-major over 2-group batches
        float sacc[8][4] = {};
        #pragma unroll
        for (int kt = 0; kt < 4; kt++) {
            #pragma unroll
            for (int gp = 0; gp < 2; gp++) {
                uint32_t kf[2][2][4];   // [split][g][frag]
                #pragma unroll
                for (int g2 = 0; g2 < 2; g2++) {
                    int g = (gp << 1) + g2;
                    uint32_t na = st
                        + (uint32_t)((g << 4) + (((lane >> 4) & 1) << 3) + (lane & 7)) * AST
                        + (kt << 5) + (((lane >> 3) & 1) << 4);
                    ldmx4(kf[0][g2], na);
                    ldmx4(kf[1][g2], na + 9216);
                }
                #pragma unroll
                for (int p = 0; p < 3; p++) {
                    const uint32_t* qa = (p == 2) ? qfl[kt] : qfh[kt];
                    const int sk = (p == 1) ? 1 : 0;
                    #pragma unroll
                    for (int g2 = 0; g2 < 2; g2++) {
                        int g = (gp << 1) + g2;
                        mma16816(sacc[2 * g],     qa, &kf[sk][g2][0]);
                        mma16816(sacc[2 * g + 1], qa, &kf[sk][g2][2]);
                    }
                }
            }
        }

        // online softmax (rows r0 = lane/4, r1 = r0+8)
        float mx0 = -1e30f, mx1 = -1e30f;
        #pragma unroll
        for (int n = 0; n < 8; n++) {
            mx0 = fmaxf(mx0, fmaxf(sacc[n][0], sacc[n][1]));
            mx1 = fmaxf(mx1, fmaxf(sacc[n][2], sacc[n][3]));
        }
        mx0 = fmaxf(mx0, __shfl_xor_sync(0xffffffffu, mx0, 1));
        mx0 = fmaxf(mx0, __shfl_xor_sync(0xffffffffu, mx0, 2));
        mx1 = fmaxf(mx1, __shfl_xor_sync(0xffffffffu, mx1, 1));
        mx1 = fmaxf(mx1, __shfl_xor_sync(0xffffffffu, mx1, 2));
        float nm0 = fmaxf(m0, mx0), nm1 = fmaxf(m1, mx1);
        float al0 = __expf(m0 - nm0), al1 = __expf(m1 - nm1);
        float rs0 = 0.f, rs1 = 0.f;
        #pragma unroll
        for (int n = 0; n < 8; n++) {
            sacc[n][0] = __expf(sacc[n][0] - nm0);
            sacc[n][1] = __expf(sacc[n][1] - nm0);
            sacc[n][2] = __expf(sacc[n][2] - nm1);
            sacc[n][3] = __expf(sacc[n][3] - nm1);
            rs0 += sacc[n][0] + sacc[n][1];
            rs1 += sacc[n][2] + sacc[n][3];
        }
        rs0 += __shfl_xor_sync(0xffffffffu, rs0, 1);
        rs0 += __shfl_xor_sync(0xffffffffu, rs0, 2);
        rs1 += __shfl_xor_sync(0xffffffffu, rs1, 1);
        rs1 += __shfl_xor_sync(0xffffffffu, rs1, 2);
        l0 = l0 * al0 + rs0; l1 = l1 * al1 + rs1;
        m0 = nm0; m1 = nm1;
        #pragma unroll
        for (int n = 0; n < 8; n++) {
            o[n][0] *= al0; o[n][1] *= al0;
            o[n][2] *= al1; o[n][3] *= al1;
        }

        // O += P V (P split in registers; V frags via ldmatrix.trans)
        #pragma unroll
        for (int kt = 0; kt < 4; kt++) {
            uint32_t ph[4], pl[4];
            psplit(sacc[2 * kt][0],     sacc[2 * kt][1],     ph[0], pl[0]);
            psplit(sacc[2 * kt][2],     sacc[2 * kt][3],     ph[1], pl[1]);
            psplit(sacc[2 * kt + 1][0], sacc[2 * kt + 1][1], ph[2], pl[2]);
            psplit(sacc[2 * kt + 1][2], sacc[2 * kt + 1][3], ph[3], pl[3]);
            #pragma unroll
            for (int gp = 0; gp < 2; gp++) {
                uint32_t vf[2][2][4];
                #pragma unroll
                for (int g2 = 0; g2 < 2; g2++) {
                    int g = (gp << 1) + g2;
                    uint32_t va = st + 18432
                        + (uint32_t)((kt << 4) + (lane & 7) + (((lane >> 3) & 1) << 3)) * AST
                        + (((g << 4) + (((lane >> 4) & 1) << 3)) << 1);
                    ldmx4t(vf[0][g2], va);
                    ldmx4t(vf[1][g2], va + 9216);
                }
                #pragma unroll
                for (int p = 0; p < 3; p++) {
                    const uint32_t* pa = (p == 2) ? pl : ph;
                    const int sv = (p == 1) ? 1 : 0;
                    #pragma unroll
                    for (int g2 = 0; g2 < 2; g2++) {
                        int g = (gp << 1) + g2;
                        mma16816(o[2 * g],     pa, &vf[sv][g2][0]);
                        mma16816(o[2 * g + 1], pa, &vf[sv][g2][2]);
                    }
                }
            }
        }
        __syncthreads();   // compute done before next iter overwrites stage
    }

    // epilogue: y = O / l -> bf16 hi/lo splits (proj input)
    float il0 = 1.f / l0, il1 = 1.f / l1;
    const int b = bh >> 4, h = bh & 15;
    const int r0 = b * 2048 + q0 + (wid << 4) + (lane >> 2);
    const int c0 = h * 64 + ((lane & 3) << 1);
    #pragma unroll
    for (int n = 0; n < 8; n++) {
        size_t o0 = (size_t)r0 * 1024 + c0 + (n << 3);
        wsplit(yhi, ylo, o0, o[n][0] * il0, o[n][1] * il0);
        wsplit(yhi, ylo, o0 + 8 * 1024, o[n][2] * il1, o[n][3] * il1);
    }
}

// ---------------------------------------------------------------------------
extern "C" void kernel_launch(void* const* d_in, const int* in_sizes, int n_in,
                              void* d_out, int out_size)
{
    const float* x     = (const float*)d_in[0];
    const float* cs    = (const float*)d_in[1];
    const float* sn    = (const float*)d_in[2];
    const float* Wqkv  = (const float*)d_in[3];
    const float* bqkv  = (const float*)d_in[4];
    const float* Wproj = (const float*)d_in[5];
    const float* bproj = (const float*)d_in[6];

    float* out   = (float*)d_out;
    float* out_y = out;
    float* out_k = out + (size_t)2 * 2048 * 1024;
    float* out_v = out_k + (size_t)2 * 16 * 2048 * 64;

    __nv_bfloat16 *xhi, *xlo, *wqh, *wql, *wph, *wpl, *yhi, *ylo;
    __nv_bfloat16 *qh, *ql, *kh, *kl, *vh, *vl;
    cudaGetSymbolAddress((void**)&xhi, g_xhi);
    cudaGetSymbolAddress((void**)&xlo, g_xlo);
    cudaGetSymbolAddress((void**)&wqh, g_wqt_hi);
    cudaGetSymbolAddress((void**)&wql, g_wqt_lo);
    cudaGetSymbolAddress((void**)&wph, g_wpt_hi);
    cudaGetSymbolAddress((void**)&wpl, g_wpt_lo);
    cudaGetSymbolAddress((void**)&yhi, g_yhi);
    cudaGetSymbolAddress((void**)&ylo, g_ylo);
    cudaGetSymbolAddress((void**)&qh, g_qh);
    cudaGetSymbolAddress((void**)&ql, g_ql);
    cudaGetSymbolAddress((void**)&kh, g_kh);
    cudaGetSymbolAddress((void**)&kl, g_kl);
    cudaGetSymbolAddress((void**)&vh, g_vh);
    cudaGetSymbolAddress((void**)&vl, g_vl);

    const int gemm_smem = 2 * STAGE_B;
    cudaFuncSetAttribute(gemm_mma<true>,
                         cudaFuncAttributeMaxDynamicSharedMemorySize, gemm_smem);
    cudaFuncSetAttribute(gemm_mma<false>,
                         cudaFuncAttributeMaxDynamicSharedMemorySize, gemm_smem);
    const int attn_smem = 2 * ASTG;   // 73728
    cudaFuncSetAttribute(attn_mma,
                         cudaFuncAttributeMaxDynamicSharedMemorySize, attn_smem);

    // 0) split conversions
    convert_split<<<4096, 256>>>(x, xhi, xlo);
    transpose_split<<<dim3(96, 32), dim3(32, 8)>>>(Wqkv, wqh, wql, 1024, 3072);
    transpose_split<<<dim3(32, 32), dim3(32, 8)>>>(Wproj, wph, wpl, 1024, 1024);

    // 1) QKV GEMM + fused bias/RoPE/scatter/split
    gemm_mma<true><<<dim3(24, 32), 256, gemm_smem>>>(
        xhi, xlo, wqh, wql, bqkv, nullptr, 4096, 3072, 1024,
        cs, sn, out_k, out_v, qh, ql, kh, kl, vh, vl);

    // 2) Attention (tensor cores, split bf16) -> y splits
    attn_mma<<<dim3(16, 32), 256, attn_smem>>>(
        qh, ql, kh, kl, vh, vl, yhi, ylo);

    // 3) Projection
    gemm_mma<false><<<dim3(8, 32), 256, gemm_smem>>>(
        yhi, ylo, wph, wpl, bproj, out_y, 4096, 1024, 1024,
        nullptr, nullptr, nullptr, nullptr,
        nullptr, nullptr, nullptr, nullptr, nullptr, nullptr);
}